// round 9
// baseline (speedup 1.0000x reference)
#include <cuda_runtime.h>
#include <cstdint>

// DeepUDI as four streaming kernels. k1b/k1c reshaped to match gru_kernel's
// proven profile (75% DRAM): few CTAs, large contiguous per-CTA streams,
// many independent LDG.128 per thread, minimal barriers.
//   K1a: w stream   -> Hn (scratch), J (scratch)      [LDS-bound ~ DRAM floor]
//   K1b: qw stream  -> Jq (scratch)   4 tiles/CTA, 128KB contiguous
//   K1c: kw stream  -> df (scratch)   2 tiles/CTA, 64KB contiguous
//   K2 : Wx/Wn stream -> GRU -> out   [unchanged]

#define NN   2048
#define RR   2
#define KK   32
#define DD   64
#define FF   64
#define DD2  128
#define HPAD 68
#define NT   (NN * RR)

__device__ float Hn_g[NT * KK * FF];   // 33.5MB
__device__ float J_g [NT * FF];        // 1MB
__device__ float Jq_g[NT * DD2];       // 2MB
__device__ float df_g[NT * FF];        // 1MB

__device__ __forceinline__ float sigm(float v) {
    return 1.f / (1.f + __expf(-v));
}

// ============ K1a: Hn = hn @ w, J = h @ w (unchanged) ==================
__global__ __launch_bounds__(256)
void k1a_kernel(const void* __restrict__ x_raw,
                const void* __restrict__ nb_raw,
                const float* __restrict__ embed,
                const float* __restrict__ w)
{
    __shared__ __align__(16) float w_s[DD * FF];
    __shared__ __align__(16) float hn_s[KK][HPAD];
    __shared__ float h_s[DD];
    __shared__ int   nb_sh[KK];
    __shared__ int   flags[2];

    const int nr  = blockIdx.x;
    const int n   = nr >> 1;
    const int tid = threadIdx.x;

    if (tid == 0) {
        const int* xi = (const int*)x_raw;
        int idx64 = (xi[1] == 0) ? 1 : 0;
        flags[0] = idx64;
        flags[1] = idx64 ? (int)((const long long*)x_raw)[n] : xi[n];
    }
    __syncthreads();
    const int idx64 = flags[0];
    const int xn    = flags[1];

    if (tid < KK) {
        long long base = (long long)nr * KK + tid;
        nb_sh[tid] = idx64 ? (int)((const long long*)nb_raw)[base]
                           : ((const int*)nb_raw)[base];
    }
    if (tid >= 64 && tid < 128)
        h_s[tid - 64] = embed[(long long)xn * DD + (tid - 64)];

    const float4* ws = (const float4*)(w + (long long)nr * (DD * FF));
    #pragma unroll
    for (int j = 0; j < 4; j++)
        ((float4*)w_s)[tid + 256 * j] = __ldg(ws + tid + 256 * j);
    __syncthreads();

    #pragma unroll
    for (int j = 0; j < 2; j++) {
        int i  = tid + 256 * j;
        int k  = i >> 4, dv = i & 15;
        *(float4*)(&hn_s[k][dv * 4]) =
            *(const float4*)(embed + (long long)nb_sh[k] * DD + dv * 4);
    }
    __syncthreads();

    const int k  = tid >> 3;
    const int g  = tid & 7;
    const int f0 = g * 8;

    float acc[8];
    #pragma unroll
    for (int j = 0; j < 8; j++) acc[j] = 0.f;

    #pragma unroll 4
    for (int d = 0; d < DD; d++) {
        float a = hn_s[k][d];
        float4 w0 = *(const float4*)&w_s[d * FF + f0];
        float4 w1 = *(const float4*)&w_s[d * FF + f0 + 4];
        acc[0] += a * w0.x; acc[1] += a * w0.y;
        acc[2] += a * w0.z; acc[3] += a * w0.w;
        acc[4] += a * w1.x; acc[5] += a * w1.y;
        acc[6] += a * w1.z; acc[7] += a * w1.w;
    }
    float* hb = Hn_g + (long long)nr * (KK * FF) + k * FF + f0;
    *(float4*)hb       = make_float4(acc[0], acc[1], acc[2], acc[3]);
    *(float4*)(hb + 4) = make_float4(acc[4], acc[5], acc[6], acc[7]);

    if (tid < FF) {
        float ja = 0.f;
        #pragma unroll 8
        for (int d = 0; d < DD; d++)
            ja += h_s[d] * w_s[d * FF + tid];
        J_g[(long long)nr * FF + tid] = ja;
    }
}

// ============ K1b: Jq = J @ qw, 4 tiles/CTA, all-float4 ================
__global__ __launch_bounds__(256)
void k1b_kernel(const float* __restrict__ qw)
{
    __shared__ float J_s[4][FF];
    __shared__ __align__(16) float part[4][8][DD2];   // 16KB

    const int t0  = blockIdx.x * 4;
    const int tid = threadIdx.x;

    // 4 tiles' J: 256 floats, one per thread
    {
        int t = tid >> 6, f = tid & 63;
        J_s[t][f] = J_g[(long long)(t0 + t) * FF + f];
    }
    __syncthreads();

    const int e4 = tid & 31;   // lane: float4 column of Jq
    const int fh = tid >> 5;   // warp: rows fh*8 .. fh*8+7

    float4 a0 = make_float4(0,0,0,0), a1 = a0, a2 = a0, a3 = a0;
    const float4* q0 = (const float4*)(qw + ((long long)(t0+0) * FF + fh*8) * DD2) + e4;
    const float4* q1 = (const float4*)(qw + ((long long)(t0+1) * FF + fh*8) * DD2) + e4;
    const float4* q2 = (const float4*)(qw + ((long long)(t0+2) * FF + fh*8) * DD2) + e4;
    const float4* q3 = (const float4*)(qw + ((long long)(t0+3) * FF + fh*8) * DD2) + e4;

    #pragma unroll
    for (int f = 0; f < 8; f++) {
        int ff = fh * 8 + f;
        float j0 = J_s[0][ff], j1 = J_s[1][ff];
        float j2 = J_s[2][ff], j3 = J_s[3][ff];
        float4 v0 = __ldg(q0 + f * 32);
        float4 v1 = __ldg(q1 + f * 32);
        float4 v2 = __ldg(q2 + f * 32);
        float4 v3 = __ldg(q3 + f * 32);
        a0.x += j0*v0.x; a0.y += j0*v0.y; a0.z += j0*v0.z; a0.w += j0*v0.w;
        a1.x += j1*v1.x; a1.y += j1*v1.y; a1.z += j1*v1.z; a1.w += j1*v1.w;
        a2.x += j2*v2.x; a2.y += j2*v2.y; a2.z += j2*v2.z; a2.w += j2*v2.w;
        a3.x += j3*v3.x; a3.y += j3*v3.y; a3.z += j3*v3.z; a3.w += j3*v3.w;
    }
    *(float4*)&part[0][fh][e4 * 4] = a0;
    *(float4*)&part[1][fh][e4 * 4] = a1;
    *(float4*)&part[2][fh][e4 * 4] = a2;
    *(float4*)&part[3][fh][e4 * 4] = a3;
    __syncthreads();

    // reduce over 8 warps: 4 tiles x 32 float4 slots = 128 threads
    if (tid < 128) {
        int t = tid >> 5, e = tid & 31;
        float4 s = make_float4(0,0,0,0);
        #pragma unroll
        for (int h = 0; h < 8; h++) {
            float4 v = *(const float4*)&part[t][h][e * 4];
            s.x += v.x; s.y += v.y; s.z += v.z; s.w += v.w;
        }
        *(float4*)(Jq_g + (long long)(t0 + t) * DD2 + e * 4) = s;
    }
}

// ============ K1c: v, scores, softmax, df — 2 tiles/CTA ================
__global__ __launch_bounds__(256)
void k1c_kernel(const float* __restrict__ kw)
{
    __shared__ __align__(16) float jq_s[2][DD2];
    __shared__ float v_s[2][FF];
    __shared__ float sc_s[2][KK];
    __shared__ __align__(16) float hn_s[2][KK][HPAD];

    const int t0  = blockIdx.x * 2;
    const int tid = threadIdx.x;
    const int k   = tid >> 3;
    const int g   = tid & 7;
    const int f0  = g * 8;

    // Jq for both tiles: 256 floats, one per thread
    {
        int t = tid >> 7, e = tid & 127;
        jq_s[t][e] = Jq_g[(long long)(t0 + t) * DD2 + e];
    }

    // Hn tiles into regs + smem (independent LDG.128)
    float4 hA[2], hB[2];
    #pragma unroll
    for (int t = 0; t < 2; t++) {
        const float* hb = Hn_g + ((long long)(t0 + t) * KK + k) * FF + f0;
        hA[t] = __ldg((const float4*)hb);
        hB[t] = __ldg((const float4*)(hb + 4));
        *(float4*)&hn_s[t][k][f0]     = hA[t];
        *(float4*)&hn_s[t][k][f0 + 4] = hB[t];
    }
    __syncthreads();

    // v[f] = sum_e kw[f,e]*Jq[e] : warps own rows, tiles interleaved
    {
        int warp = tid >> 5, lane = tid & 31;
        float4 qv0 = ((const float4*)jq_s[0])[lane];
        float4 qv1 = ((const float4*)jq_s[1])[lane];
        const float4* kr0 = (const float4*)(kw + ((long long)(t0+0) * FF + warp*8) * DD2) + lane;
        const float4* kr1 = (const float4*)(kw + ((long long)(t0+1) * FF + warp*8) * DD2) + lane;
        #pragma unroll
        for (int i = 0; i < 8; i++) {
            int f = warp * 8 + i;
            float4 k0 = __ldg(kr0 + i * 32);
            float4 k1 = __ldg(kr1 + i * 32);
            float p0 = k0.x*qv0.x + k0.y*qv0.y + k0.z*qv0.z + k0.w*qv0.w;
            float p1 = k1.x*qv1.x + k1.y*qv1.y + k1.z*qv1.z + k1.w*qv1.w;
            #pragma unroll
            for (int off = 16; off > 0; off >>= 1) {
                p0 += __shfl_xor_sync(0xffffffffu, p0, off);
                p1 += __shfl_xor_sync(0xffffffffu, p1, off);
            }
            if (lane == 0) { v_s[0][f] = p0; v_s[1][f] = p1; }
        }
    }
    __syncthreads();

    // scores[k] = Hn[k,:].v from live regs
    #pragma unroll
    for (int t = 0; t < 2; t++) {
        float s = hA[t].x*v_s[t][f0]   + hA[t].y*v_s[t][f0+1]
                + hA[t].z*v_s[t][f0+2] + hA[t].w*v_s[t][f0+3]
                + hB[t].x*v_s[t][f0+4] + hB[t].y*v_s[t][f0+5]
                + hB[t].z*v_s[t][f0+6] + hB[t].w*v_s[t][f0+7];
        s += __shfl_xor_sync(0xffffffffu, s, 1);
        s += __shfl_xor_sync(0xffffffffu, s, 2);
        s += __shfl_xor_sync(0xffffffffu, s, 4);
        if (g == 0) sc_s[t][k] = s;
    }
    __syncthreads();

    // softmax over K=32: warp 0 -> tile 0, warp 1 -> tile 1
    if (tid < 64) {
        int t = tid >> 5, lane = tid & 31;
        float s = sc_s[t][lane];
        float m = s;
        #pragma unroll
        for (int off = 16; off > 0; off >>= 1)
            m = fmaxf(m, __shfl_xor_sync(0xffffffffu, m, off));
        float e = __expf(s - m);
        float sum = e;
        #pragma unroll
        for (int off = 16; off > 0; off >>= 1)
            sum += __shfl_xor_sync(0xffffffffu, sum, off);
        sc_s[t][lane] = e / sum;
    }
    __syncthreads();

    // df[f] = sum_k E[k]*Hn[k,f] : 128 threads cover 2 tiles
    if (tid < 128) {
        int t = tid >> 6, f = tid & 63;
        float da = 0.f;
        #pragma unroll
        for (int kk = 0; kk < KK; kk++)
            da += sc_s[t][kk] * hn_s[t][kk][f];
        df_g[(long long)(t0 + t) * FF + f] = da;
    }
}

// ============ K2: GRU + combine (unchanged, 76% DRAM) ==================
__global__ __launch_bounds__(256)
void gru_kernel(const void* __restrict__ x_raw,
                const float* __restrict__ embed,
                const float* __restrict__ Wx,
                const float* __restrict__ Wn,
                const float* __restrict__ bx,
                const float* __restrict__ bn,
                float* __restrict__ out)
{
    __shared__ float h_s[DD];
    __shared__ float df_s[RR][FF];
    __shared__ __align__(16) float part[RR][8][5][FF];
    __shared__ __align__(16) float red[RR][6][FF];
    __shared__ float rdf_s[RR][FF];
    __shared__ float gru_s[RR][FF];
    __shared__ int   flags[2];

    const int n   = blockIdx.x;
    const int tid = threadIdx.x;
    const int r   = tid >> 7;
    const int wg  = tid & 127;

    if (tid == 0) {
        const int* xi = (const int*)x_raw;
        int idx64 = (xi[1] == 0) ? 1 : 0;
        flags[0] = idx64;
        flags[1] = idx64 ? (int)((const long long*)x_raw)[n] : xi[n];
    }
    __syncthreads();
    const int xn = flags[1];

    if (tid < DD) h_s[tid] = embed[(long long)xn * DD + tid];
    if (wg < FF)  df_s[r][wg] = df_g[((long long)n * RR + r) * FF + wg];
    __syncthreads();

    const long long nr = (long long)n * RR + r;
    const float* Wxr = Wx + nr * (3 * DD * FF);
    const float* Wnr = Wn + nr * (3 * FF * FF);
    const float* bxr = bx + nr * (3 * FF);
    const float* bnr = bn + nr * (3 * FF);

    const int fg = wg & 15;
    const int ds = wg >> 4;
    const int f4 = fg * 4;

    float4 a0 = make_float4(0,0,0,0), a1 = a0, a2v = a0, a3 = a0, a4 = a0;
    #pragma unroll
    for (int dd = 0; dd < 8; dd++) {
        int d = ds * 8 + dd;
        float hd  = h_s[d];
        float dfd = df_s[r][d];
        float4 x0 = __ldg((const float4*)(Wxr + (0*DD + d)*FF + f4));
        float4 x1 = __ldg((const float4*)(Wxr + (1*DD + d)*FF + f4));
        float4 x2 = __ldg((const float4*)(Wxr + (2*DD + d)*FF + f4));
        float4 n0 = __ldg((const float4*)(Wnr + (0*FF + d)*FF + f4));
        float4 n1 = __ldg((const float4*)(Wnr + (1*FF + d)*FF + f4));
        a0.x += hd*x0.x;  a0.y += hd*x0.y;  a0.z += hd*x0.z;  a0.w += hd*x0.w;
        a1.x += hd*x1.x;  a1.y += hd*x1.y;  a1.z += hd*x1.z;  a1.w += hd*x1.w;
        a2v.x+= hd*x2.x;  a2v.y+= hd*x2.y;  a2v.z+= hd*x2.z;  a2v.w+= hd*x2.w;
        a3.x += dfd*n0.x; a3.y += dfd*n0.y; a3.z += dfd*n0.z; a3.w += dfd*n0.w;
        a4.x += dfd*n1.x; a4.y += dfd*n1.y; a4.z += dfd*n1.z; a4.w += dfd*n1.w;
    }
    *(float4*)&part[r][ds][0][f4] = a0;
    *(float4*)&part[r][ds][1][f4] = a1;
    *(float4*)&part[r][ds][2][f4] = a2v;
    *(float4*)&part[r][ds][3][f4] = a3;
    *(float4*)&part[r][ds][4][f4] = a4;
    __syncthreads();

    if (wg < 80) {
        int gate = wg >> 4, fgi = wg & 15;
        float4 s = make_float4(0,0,0,0);
        #pragma unroll
        for (int d2 = 0; d2 < 8; d2++) {
            float4 v = *(const float4*)&part[r][d2][gate][fgi * 4];
            s.x += v.x; s.y += v.y; s.z += v.z; s.w += v.w;
        }
        *(float4*)&red[r][gate][fgi * 4] = s;
    }
    __syncthreads();

    float xh_v = 0.f, z_v = 0.f, dff = 0.f;
    if (wg < FF) {
        int f = wg;
        float xr = red[r][0][f] + __ldg(bxr + f);
        float xz = red[r][1][f] + __ldg(bxr + FF + f);
        xh_v     = red[r][2][f] + __ldg(bxr + 2*FF + f);
        float rg = sigm(xr + red[r][3][f] + __ldg(bnr + f));
        z_v      = sigm(xz + red[r][4][f] + __ldg(bnr + FF + f));
        dff = df_s[r][f];
        rdf_s[r][f] = rg * dff;
    }
    __syncthreads();

    float4 c = make_float4(0,0,0,0);
    #pragma unroll
    for (int dd = 0; dd < 8; dd++) {
        int d = ds * 8 + dd;
        float rd = rdf_s[r][d];
        float4 n2 = __ldg((const float4*)(Wnr + (2*FF + d)*FF + f4));
        c.x += rd*n2.x; c.y += rd*n2.y; c.z += rd*n2.z; c.w += rd*n2.w;
    }
    *(float4*)&part[r][ds][0][f4] = c;
    __syncthreads();

    if (wg < 16) {
        float4 s = make_float4(0,0,0,0);
        #pragma unroll
        for (int d2 = 0; d2 < 8; d2++) {
            float4 v = *(const float4*)&part[r][d2][0][wg * 4];
            s.x += v.x; s.y += v.y; s.z += v.z; s.w += v.w;
        }
        *(float4*)&red[r][5][wg * 4] = s;
    }
    __syncthreads();

    if (wg < FF) {
        float hc = tanhf(xh_v + red[r][5][wg] + __ldg(bnr + 2*FF + wg));
        gru_s[r][wg] = z_v * dff + (1.f - z_v) * hc;
    }
    __syncthreads();

    if (tid < FF)
        out[(long long)n * FF + tid] =
            tanhf(0.5f * (gru_s[0][tid] + gru_s[1][tid]));
}

extern "C" void kernel_launch(void* const* d_in, const int* in_sizes, int n_in,
                              void* d_out, int out_size) {
    (void)in_sizes; (void)n_in; (void)out_size;
    k1a_kernel<<<NT, 256>>>(
        d_in[0], d_in[1],
        (const float*)d_in[2],         // embed
        (const float*)d_in[3]);        // w
    k1b_kernel<<<NT / 4, 256>>>(
        (const float*)d_in[4]);        // qw
    k1c_kernel<<<NT / 2, 256>>>(
        (const float*)d_in[5]);        // kw
    gru_kernel<<<NN, 256>>>(
        d_in[0],
        (const float*)d_in[2],         // embed
        (const float*)d_in[6],         // Wx
        (const float*)d_in[7],         // Wn
        (const float*)d_in[8],         // bx
        (const float*)d_in[9],         // bn
        (float*)d_out);
}

// round 10
// speedup vs baseline: 1.0603x; 1.0603x over previous
#include <cuda_runtime.h>
#include <cstdint>

// DeepUDI, load-first streaming kernels. Rule: every DRAM stream is issued in
// the kernel's first instructions, before any barrier or computed dependency,
// so CTA staggering keeps HBM busy through the compute tails (gru pattern).
//   kJ : J  = h @ w        (w stream, 67MB)
//   kJq: Jq = J @ qw       (qw stream, 134MB)   [R9 k1b shape]
//   kB : v = kw@Jq; Hn = hn@w; scores; softmax; df
//        (kw+w streams 201MB, all loads front-issued; GEMM is smem-only tail)
//   gru: unchanged (76% DRAM)

#define NN   2048
#define RR   2
#define KK   32
#define DD   64
#define FF   64
#define DD2  128
#define HPAD 68
#define NT   (NN * RR)

__device__ float J_g [NT * FF];        // 1MB scratch
__device__ float Jq_g[NT * DD2];       // 2MB scratch
__device__ float df_g[NT * FF];        // 1MB scratch

__device__ __forceinline__ float sigm(float v) {
    return 1.f / (1.f + __expf(-v));
}

// ============ kJ: J = h @ w (both relations per node) ==================
__global__ __launch_bounds__(256)
void kJ_kernel(const void* __restrict__ x_raw,
               const float* __restrict__ embed,
               const float* __restrict__ w)
{
    __shared__ float h_s[DD];
    __shared__ __align__(16) float part[RR][8][FF];
    __shared__ int flags[2];

    const int n   = blockIdx.x;
    const int tid = threadIdx.x;
    const int r   = tid >> 7;
    const int wg  = tid & 127;
    const int ds  = wg >> 4;           // 8 d-slices of 8
    const int f4  = (wg & 15) * 4;

    // w loads FIRST: 8 independent LDG.128, no deps on anything computed
    const float* wr = w + ((long long)n * RR + r) * (DD * FF);
    float4 wv[8];
    #pragma unroll
    for (int dd = 0; dd < 8; dd++)
        wv[dd] = __ldg((const float4*)(wr + (ds * 8 + dd) * FF + f4));

    if (tid == 0) {
        const int* xi = (const int*)x_raw;
        int idx64 = (xi[1] == 0) ? 1 : 0;
        flags[0] = idx64;
        flags[1] = idx64 ? (int)((const long long*)x_raw)[n] : xi[n];
    }
    __syncthreads();
    if (tid < DD) h_s[tid] = embed[(long long)flags[1] * DD + tid];
    __syncthreads();

    float4 a = make_float4(0, 0, 0, 0);
    #pragma unroll
    for (int dd = 0; dd < 8; dd++) {
        float hd = h_s[ds * 8 + dd];
        a.x += hd * wv[dd].x; a.y += hd * wv[dd].y;
        a.z += hd * wv[dd].z; a.w += hd * wv[dd].w;
    }
    *(float4*)&part[r][ds][f4] = a;
    __syncthreads();

    if (tid < 128) {
        int rr = tid >> 6, f = tid & 63;
        float s = 0.f;
        #pragma unroll
        for (int d2 = 0; d2 < 8; d2++) s += part[rr][d2][f];
        J_g[((long long)n * RR + rr) * FF + f] = s;
    }
}

// ============ kJq: Jq = J @ qw, 4 tiles/CTA ============================
__global__ __launch_bounds__(256)
void kJq_kernel(const float* __restrict__ qw)
{
    __shared__ float J_s[4][FF];
    __shared__ __align__(16) float part[4][8][DD2];

    const int t0  = blockIdx.x * 4;
    const int tid = threadIdx.x;

    {
        int t = tid >> 6, f = tid & 63;
        J_s[t][f] = J_g[(long long)(t0 + t) * FF + f];
    }
    __syncthreads();

    const int e4 = tid & 31;
    const int fh = tid >> 5;

    float4 a0 = make_float4(0,0,0,0), a1 = a0, a2 = a0, a3 = a0;
    const float4* q0 = (const float4*)(qw + ((long long)(t0+0) * FF + fh*8) * DD2) + e4;
    const float4* q1 = (const float4*)(qw + ((long long)(t0+1) * FF + fh*8) * DD2) + e4;
    const float4* q2 = (const float4*)(qw + ((long long)(t0+2) * FF + fh*8) * DD2) + e4;
    const float4* q3 = (const float4*)(qw + ((long long)(t0+3) * FF + fh*8) * DD2) + e4;

    #pragma unroll
    for (int f = 0; f < 8; f++) {
        int ff = fh * 8 + f;
        float j0 = J_s[0][ff], j1 = J_s[1][ff];
        float j2 = J_s[2][ff], j3 = J_s[3][ff];
        float4 v0 = __ldg(q0 + f * 32);
        float4 v1 = __ldg(q1 + f * 32);
        float4 v2 = __ldg(q2 + f * 32);
        float4 v3 = __ldg(q3 + f * 32);
        a0.x += j0*v0.x; a0.y += j0*v0.y; a0.z += j0*v0.z; a0.w += j0*v0.w;
        a1.x += j1*v1.x; a1.y += j1*v1.y; a1.z += j1*v1.z; a1.w += j1*v1.w;
        a2.x += j2*v2.x; a2.y += j2*v2.y; a2.z += j2*v2.z; a2.w += j2*v2.w;
        a3.x += j3*v3.x; a3.y += j3*v3.y; a3.z += j3*v3.z; a3.w += j3*v3.w;
    }
    *(float4*)&part[0][fh][e4 * 4] = a0;
    *(float4*)&part[1][fh][e4 * 4] = a1;
    *(float4*)&part[2][fh][e4 * 4] = a2;
    *(float4*)&part[3][fh][e4 * 4] = a3;
    __syncthreads();

    if (tid < 128) {
        int t = tid >> 5, e = tid & 31;
        float4 s = make_float4(0,0,0,0);
        #pragma unroll
        for (int h = 0; h < 8; h++) {
            float4 v = *(const float4*)&part[t][h][e * 4];
            s.x += v.x; s.y += v.y; s.z += v.z; s.w += v.w;
        }
        *(float4*)(Jq_g + (long long)(t0 + t) * DD2 + e * 4) = s;
    }
}

// ============ kB: v, Hn GEMM, scores, softmax, df ======================
// All DRAM loads (Jq, kw, w) issue at the top; the GEMM + attention tail
// runs entirely from smem/regs.
__global__ __launch_bounds__(256)
void kB_kernel(const void* __restrict__ x_raw,
               const void* __restrict__ nb_raw,
               const float* __restrict__ embed,
               const float* __restrict__ w,
               const float* __restrict__ kw)
{
    __shared__ __align__(16) float w_s[DD * FF];
    __shared__ __align__(16) float hn_s[KK][HPAD];
    __shared__ float v_s[FF];
    __shared__ float sc_s[KK];
    __shared__ int   nb_sh[KK];
    __shared__ int   flags[2];

    const int nr  = blockIdx.x;
    const int n   = nr >> 1;
    const int tid = threadIdx.x;
    const int warp = tid >> 5, lane = tid & 31;

    // ---- front-issued DRAM loads (no computed dependencies) ------------
    // Jq slice for this thread's v lanes (Jq_g is L2-hot, 2MB)
    float4 qv = __ldg((const float4*)(Jq_g + (long long)nr * DD2) + lane);

    // kw rows for this warp: 8 independent LDG.128 into regs
    const float4* kr = (const float4*)(kw + ((long long)nr * FF + warp * 8) * DD2) + lane;
    float4 kv[8];
    #pragma unroll
    for (int i = 0; i < 8; i++) kv[i] = __ldg(kr + i * 32);

    // w stream into regs (staged to smem after)
    const float4* ws = (const float4*)(w + (long long)nr * (DD * FF));
    float4 wt[4];
    #pragma unroll
    for (int j = 0; j < 4; j++) wt[j] = __ldg(ws + tid + 256 * j);

    if (tid == 0) {
        const int* xi = (const int*)x_raw;
        int idx64 = (xi[1] == 0) ? 1 : 0;
        flags[0] = idx64;
        flags[1] = idx64 ? (int)((const long long*)x_raw)[n] : xi[n];
    }
    __syncthreads();
    const int idx64 = flags[0];

    if (tid < KK) {
        long long base = (long long)nr * KK + tid;
        nb_sh[tid] = idx64 ? (int)((const long long*)nb_raw)[base]
                           : ((const int*)nb_raw)[base];
    }
    #pragma unroll
    for (int j = 0; j < 4; j++) ((float4*)w_s)[tid + 256 * j] = wt[j];
    __syncthreads();

    // hn gather (embed rows are L2-resident)
    #pragma unroll
    for (int j = 0; j < 2; j++) {
        int i  = tid + 256 * j;
        int kk = i >> 4, dv = i & 15;
        *(float4*)(&hn_s[kk][dv * 4]) =
            *(const float4*)(embed + (long long)nb_sh[kk] * DD + dv * 4);
    }

    // ---- v[f] = sum_e kw[f,e]*Jq[e] (kv regs already in flight) --------
    #pragma unroll
    for (int i = 0; i < 8; i++) {
        float p = kv[i].x*qv.x + kv[i].y*qv.y + kv[i].z*qv.z + kv[i].w*qv.w;
        #pragma unroll
        for (int off = 16; off > 0; off >>= 1)
            p += __shfl_xor_sync(0xffffffffu, p, off);
        if (lane == 0) v_s[warp * 8 + i] = p;
    }
    __syncthreads();   // hn_s + v_s ready

    // ---- Hn = hn @ w (pure smem tail) ----------------------------------
    const int k  = tid >> 3;
    const int g  = tid & 7;
    const int f0 = g * 8;

    float acc[8];
    #pragma unroll
    for (int j = 0; j < 8; j++) acc[j] = 0.f;

    #pragma unroll 4
    for (int d = 0; d < DD; d++) {
        float a = hn_s[k][d];
        float4 w0 = *(const float4*)&w_s[d * FF + f0];
        float4 w1 = *(const float4*)&w_s[d * FF + f0 + 4];
        acc[0] += a * w0.x; acc[1] += a * w0.y;
        acc[2] += a * w0.z; acc[3] += a * w0.w;
        acc[4] += a * w1.x; acc[5] += a * w1.y;
        acc[6] += a * w1.z; acc[7] += a * w1.w;
    }
    __syncwarp();
    // overwrite hn row with Hn (row k touched only by this warp's 8 lanes)
    *(float4*)&hn_s[k][f0]     = make_float4(acc[0], acc[1], acc[2], acc[3]);
    *(float4*)&hn_s[k][f0 + 4] = make_float4(acc[4], acc[5], acc[6], acc[7]);

    // ---- scores[k] = Hn[k,:].v -----------------------------------------
    {
        float s = 0.f;
        #pragma unroll
        for (int j = 0; j < 8; j++) s += acc[j] * v_s[f0 + j];
        s += __shfl_xor_sync(0xffffffffu, s, 1);
        s += __shfl_xor_sync(0xffffffffu, s, 2);
        s += __shfl_xor_sync(0xffffffffu, s, 4);
        if (g == 0) sc_s[k] = s;
    }
    __syncthreads();

    // ---- softmax over K=32 (warp 0) ------------------------------------
    if (tid < 32) {
        float s = sc_s[tid];
        float m = s;
        #pragma unroll
        for (int off = 16; off > 0; off >>= 1)
            m = fmaxf(m, __shfl_xor_sync(0xffffffffu, m, off));
        float e = __expf(s - m);
        float sum = e;
        #pragma unroll
        for (int off = 16; off > 0; off >>= 1)
            sum += __shfl_xor_sync(0xffffffffu, sum, off);
        sc_s[tid] = e / sum;
    }
    __syncthreads();

    // ---- df[f] = sum_k E[k]*Hn[k,f] ------------------------------------
    if (tid < FF) {
        float da = 0.f;
        #pragma unroll
        for (int kk = 0; kk < KK; kk++)
            da += sc_s[kk] * hn_s[kk][tid];
        df_g[(long long)nr * FF + tid] = da;
    }
}

// ============ gru: GRU + combine (unchanged, 76% DRAM) =================
__global__ __launch_bounds__(256)
void gru_kernel(const void* __restrict__ x_raw,
                const float* __restrict__ embed,
                const float* __restrict__ Wx,
                const float* __restrict__ Wn,
                const float* __restrict__ bx,
                const float* __restrict__ bn,
                float* __restrict__ out)
{
    __shared__ float h_s[DD];
    __shared__ float df_s[RR][FF];
    __shared__ __align__(16) float part[RR][8][5][FF];
    __shared__ __align__(16) float red[RR][6][FF];
    __shared__ float rdf_s[RR][FF];
    __shared__ float gru_s[RR][FF];
    __shared__ int   flags[2];

    const int n   = blockIdx.x;
    const int tid = threadIdx.x;
    const int r   = tid >> 7;
    const int wg  = tid & 127;

    if (tid == 0) {
        const int* xi = (const int*)x_raw;
        int idx64 = (xi[1] == 0) ? 1 : 0;
        flags[0] = idx64;
        flags[1] = idx64 ? (int)((const long long*)x_raw)[n] : xi[n];
    }
    __syncthreads();
    const int xn = flags[1];

    if (tid < DD) h_s[tid] = embed[(long long)xn * DD + tid];
    if (wg < FF)  df_s[r][wg] = df_g[((long long)n * RR + r) * FF + wg];
    __syncthreads();

    const long long nr = (long long)n * RR + r;
    const float* Wxr = Wx + nr * (3 * DD * FF);
    const float* Wnr = Wn + nr * (3 * FF * FF);
    const float* bxr = bx + nr * (3 * FF);
    const float* bnr = bn + nr * (3 * FF);

    const int fg = wg & 15;
    const int ds = wg >> 4;
    const int f4 = fg * 4;

    float4 a0 = make_float4(0,0,0,0), a1 = a0, a2v = a0, a3 = a0, a4 = a0;
    #pragma unroll
    for (int dd = 0; dd < 8; dd++) {
        int d = ds * 8 + dd;
        float hd  = h_s[d];
        float dfd = df_s[r][d];
        float4 x0 = __ldg((const float4*)(Wxr + (0*DD + d)*FF + f4));
        float4 x1 = __ldg((const float4*)(Wxr + (1*DD + d)*FF + f4));
        float4 x2 = __ldg((const float4*)(Wxr + (2*DD + d)*FF + f4));
        float4 n0 = __ldg((const float4*)(Wnr + (0*FF + d)*FF + f4));
        float4 n1 = __ldg((const float4*)(Wnr + (1*FF + d)*FF + f4));
        a0.x += hd*x0.x;  a0.y += hd*x0.y;  a0.z += hd*x0.z;  a0.w += hd*x0.w;
        a1.x += hd*x1.x;  a1.y += hd*x1.y;  a1.z += hd*x1.z;  a1.w += hd*x1.w;
        a2v.x+= hd*x2.x;  a2v.y+= hd*x2.y;  a2v.z+= hd*x2.z;  a2v.w+= hd*x2.w;
        a3.x += dfd*n0.x; a3.y += dfd*n0.y; a3.z += dfd*n0.z; a3.w += dfd*n0.w;
        a4.x += dfd*n1.x; a4.y += dfd*n1.y; a4.z += dfd*n1.z; a4.w += dfd*n1.w;
    }
    *(float4*)&part[r][ds][0][f4] = a0;
    *(float4*)&part[r][ds][1][f4] = a1;
    *(float4*)&part[r][ds][2][f4] = a2v;
    *(float4*)&part[r][ds][3][f4] = a3;
    *(float4*)&part[r][ds][4][f4] = a4;
    __syncthreads();

    if (wg < 80) {
        int gate = wg >> 4, fgi = wg & 15;
        float4 s = make_float4(0,0,0,0);
        #pragma unroll
        for (int d2 = 0; d2 < 8; d2++) {
            float4 v = *(const float4*)&part[r][d2][gate][fgi * 4];
            s.x += v.x; s.y += v.y; s.z += v.z; s.w += v.w;
        }
        *(float4*)&red[r][gate][fgi * 4] = s;
    }
    __syncthreads();

    float xh_v = 0.f, z_v = 0.f, dff = 0.f;
    if (wg < FF) {
        int f = wg;
        float xr = red[r][0][f] + __ldg(bxr + f);
        float xz = red[r][1][f] + __ldg(bxr + FF + f);
        xh_v     = red[r][2][f] + __ldg(bxr + 2*FF + f);
        float rg = sigm(xr + red[r][3][f] + __ldg(bnr + f));
        z_v      = sigm(xz + red[r][4][f] + __ldg(bnr + FF + f));
        dff = df_s[r][f];
        rdf_s[r][f] = rg * dff;
    }
    __syncthreads();

    float4 c = make_float4(0,0,0,0);
    #pragma unroll
    for (int dd = 0; dd < 8; dd++) {
        int d = ds * 8 + dd;
        float rd = rdf_s[r][d];
        float4 n2 = __ldg((const float4*)(Wnr + (2*FF + d)*FF + f4));
        c.x += rd*n2.x; c.y += rd*n2.y; c.z += rd*n2.z; c.w += rd*n2.w;
    }
    *(float4*)&part[r][ds][0][f4] = c;
    __syncthreads();

    if (wg < 16) {
        float4 s = make_float4(0,0,0,0);
        #pragma unroll
        for (int d2 = 0; d2 < 8; d2++) {
            float4 v = *(const float4*)&part[r][d2][0][wg * 4];
            s.x += v.x; s.y += v.y; s.z += v.z; s.w += v.w;
        }
        *(float4*)&red[r][5][wg * 4] = s;
    }
    __syncthreads();

    if (wg < FF) {
        float hc = tanhf(xh_v + red[r][5][wg] + __ldg(bnr + 2*FF + wg));
        gru_s[r][wg] = z_v * dff + (1.f - z_v) * hc;
    }
    __syncthreads();

    if (tid < FF)
        out[(long long)n * FF + tid] =
            tanhf(0.5f * (gru_s[0][tid] + gru_s[1][tid]));
}

extern "C" void kernel_launch(void* const* d_in, const int* in_sizes, int n_in,
                              void* d_out, int out_size) {
    (void)in_sizes; (void)n_in; (void)out_size;
    kJ_kernel<<<NN, 256>>>(
        d_in[0],
        (const float*)d_in[2],         // embed
        (const float*)d_in[3]);        // w
    kJq_kernel<<<NT / 4, 256>>>(
        (const float*)d_in[4]);        // qw
    kB_kernel<<<NT, 256>>>(
        d_in[0], d_in[1],
        (const float*)d_in[2],         // embed
        (const float*)d_in[3],         // w
        (const float*)d_in[5]);        // kw
    gru_kernel<<<NN, 256>>>(
        d_in[0],
        (const float*)d_in[2],         // embed
        (const float*)d_in[6],         // Wx
        (const float*)d_in[7],         // Wn
        (const float*)d_in[8],         // bx
        (const float*)d_in[9],         // bn
        (float*)d_out);
}

// round 11
// speedup vs baseline: 1.4373x; 1.3556x over previous
#include <cuda_runtime.h>
#include <cstdint>

// DeepUDI, four gru-shaped streaming kernels. Key algebra: Hn is never
// materialized — scores = hn@(w@(kw@Jq)), df = (E@hn)@w — which cuts
// attention compute 9x (580K -> 64K FLOP/tile) and makes every kernel
// purely stream-bound with dependency-free DRAM consumption.
//   kJ  : w stream (67MB)   -> J
//   kJq : qw stream (134MB) -> Jq
//   kCD : kw+w streams (201MB) -> v -> u -> scores -> softmax -> g -> df
//   gru : Wx/Wn stream (393MB) -> out   [unchanged, 76% DRAM]

#define NN   2048
#define RR   2
#define KK   32
#define DD   64
#define FF   64
#define DD2  128
#define HPAD 68
#define NT   (NN * RR)

__device__ float J_g [NT * FF];        // 1MB scratch
__device__ float Jq_g[NT * DD2];       // 2MB scratch
__device__ float df_g[NT * FF];        // 1MB scratch

__device__ __forceinline__ float sigm(float v) {
    return 1.f / (1.f + __expf(-v));
}

// ============ kJ: J = h @ w (both relations per node) ==================
__global__ __launch_bounds__(256)
void kJ_kernel(const void* __restrict__ x_raw,
               const float* __restrict__ embed,
               const float* __restrict__ w)
{
    __shared__ float h_s[DD];
    __shared__ __align__(16) float part[RR][8][FF];
    __shared__ int flags[2];

    const int n   = blockIdx.x;
    const int tid = threadIdx.x;
    const int r   = tid >> 7;
    const int wg  = tid & 127;
    const int ds  = wg >> 4;
    const int f4  = (wg & 15) * 4;

    // w loads FIRST: 8 independent LDG.128
    const float* wr = w + ((long long)n * RR + r) * (DD * FF);
    float4 wv[8];
    #pragma unroll
    for (int dd = 0; dd < 8; dd++)
        wv[dd] = __ldg((const float4*)(wr + (ds * 8 + dd) * FF + f4));

    if (tid == 0) {
        const int* xi = (const int*)x_raw;
        int idx64 = (xi[1] == 0) ? 1 : 0;
        flags[0] = idx64;
        flags[1] = idx64 ? (int)((const long long*)x_raw)[n] : xi[n];
    }
    __syncthreads();
    if (tid < DD) h_s[tid] = embed[(long long)flags[1] * DD + tid];
    __syncthreads();

    float4 a = make_float4(0, 0, 0, 0);
    #pragma unroll
    for (int dd = 0; dd < 8; dd++) {
        float hd = h_s[ds * 8 + dd];
        a.x += hd * wv[dd].x; a.y += hd * wv[dd].y;
        a.z += hd * wv[dd].z; a.w += hd * wv[dd].w;
    }
    *(float4*)&part[r][ds][f4] = a;
    __syncthreads();

    if (tid < 128) {
        int rr = tid >> 6, f = tid & 63;
        float s = 0.f;
        #pragma unroll
        for (int d2 = 0; d2 < 8; d2++) s += part[rr][d2][f];
        J_g[((long long)n * RR + rr) * FF + f] = s;
    }
}

// ============ kJq: Jq = J @ qw, 4 tiles/CTA ============================
__global__ __launch_bounds__(256)
void kJq_kernel(const float* __restrict__ qw)
{
    __shared__ float J_s[4][FF];
    __shared__ __align__(16) float part[4][8][DD2];

    const int t0  = blockIdx.x * 4;
    const int tid = threadIdx.x;

    {
        int t = tid >> 6, f = tid & 63;
        J_s[t][f] = J_g[(long long)(t0 + t) * FF + f];
    }
    __syncthreads();

    const int e4 = tid & 31;
    const int fh = tid >> 5;

    float4 a0 = make_float4(0,0,0,0), a1 = a0, a2 = a0, a3 = a0;
    const float4* q0 = (const float4*)(qw + ((long long)(t0+0) * FF + fh*8) * DD2) + e4;
    const float4* q1 = (const float4*)(qw + ((long long)(t0+1) * FF + fh*8) * DD2) + e4;
    const float4* q2 = (const float4*)(qw + ((long long)(t0+2) * FF + fh*8) * DD2) + e4;
    const float4* q3 = (const float4*)(qw + ((long long)(t0+3) * FF + fh*8) * DD2) + e4;

    #pragma unroll
    for (int f = 0; f < 8; f++) {
        int ff = fh * 8 + f;
        float j0 = J_s[0][ff], j1 = J_s[1][ff];
        float j2 = J_s[2][ff], j3 = J_s[3][ff];
        float4 v0 = __ldg(q0 + f * 32);
        float4 v1 = __ldg(q1 + f * 32);
        float4 v2 = __ldg(q2 + f * 32);
        float4 v3 = __ldg(q3 + f * 32);
        a0.x += j0*v0.x; a0.y += j0*v0.y; a0.z += j0*v0.z; a0.w += j0*v0.w;
        a1.x += j1*v1.x; a1.y += j1*v1.y; a1.z += j1*v1.z; a1.w += j1*v1.w;
        a2.x += j2*v2.x; a2.y += j2*v2.y; a2.z += j2*v2.z; a2.w += j2*v2.w;
        a3.x += j3*v3.x; a3.y += j3*v3.y; a3.z += j3*v3.z; a3.w += j3*v3.w;
    }
    *(float4*)&part[0][fh][e4 * 4] = a0;
    *(float4*)&part[1][fh][e4 * 4] = a1;
    *(float4*)&part[2][fh][e4 * 4] = a2;
    *(float4*)&part[3][fh][e4 * 4] = a3;
    __syncthreads();

    if (tid < 128) {
        int t = tid >> 5, e = tid & 31;
        float4 s = make_float4(0,0,0,0);
        #pragma unroll
        for (int h = 0; h < 8; h++) {
            float4 v = *(const float4*)&part[t][h][e * 4];
            s.x += v.x; s.y += v.y; s.z += v.z; s.w += v.w;
        }
        *(float4*)(Jq_g + (long long)(t0 + t) * DD2 + e * 4) = s;
    }
}

// ============ kCD: v = kw@Jq; u = w@v; scores; softmax; g; df ==========
// One node per CTA (both relations). All DRAM streams (kw 64KB + w 32KB)
// consumed in a single phase after one barrier; the attention tail is
// ~50K FLOP of smem-only work.
struct CDSmem {
    float w [RR][DD * FF];    // 32KB  (also reused for df column reads)
    float hn[RR][KK][HPAD];   // 17.4KB
    float jq[RR][DD2];
    float v [RR][FF];
    float u [RR][FF];
    float sc[RR][KK];
    float g [RR][FF];
    int   nb[RR][KK];
};
#define CD_SMEM_BYTES ((int)sizeof(CDSmem))

__global__ __launch_bounds__(256)
void kCD_kernel(const void* __restrict__ x_raw,
                const void* __restrict__ nb_raw,
                const float* __restrict__ embed,
                const float* __restrict__ w,
                const float* __restrict__ kw)
{
    extern __shared__ __align__(16) char smem_raw[];
    CDSmem* S = (CDSmem*)smem_raw;

    const int n    = blockIdx.x;
    const int tid  = threadIdx.x;
    const int wp   = tid >> 5;
    const int lane = tid & 31;
    const int t    = wp >> 2;          // relation handled by this warp
    const int ww   = wp & 3;           // warp within relation

    // per-thread dtype detect (L1-broadcast read, no smem dependency)
    const int idx64 = (((const int*)x_raw)[1] == 0) ? 1 : 0;

    // tiny L2 reads: Jq (one float/thread) + nb indices
    {
        int tt = tid >> 7, e = tid & 127;
        S->jq[tt][e] = Jq_g[((long long)n * RR + tt) * DD2 + e];
    }
    if (tid < 64) {
        int tt = tid >> 5, kk = tid & 31;
        long long base = ((long long)n * RR + tt) * KK + kk;
        S->nb[tt][kk] = idx64 ? (int)((const long long*)nb_raw)[base]
                              : ((const int*)nb_raw)[base];
    }
    __syncthreads();

    // ---- single stream phase: w copy + kw->v + hn gather ---------------
    // w: 2 tiles contiguous, 2048 float4, 8 per thread (front-issued)
    const float4* wsrc = (const float4*)(w + (long long)n * RR * (DD * FF));
    float4 wreg[8];
    #pragma unroll
    for (int j = 0; j < 8; j++)
        wreg[j] = __ldg(wsrc + tid + 256 * j);

    // v[f] = sum_e kw[f,e]*Jq[e] : warp ww owns rows ww*16..+15 of tile t
    {
        const float4* kr = (const float4*)
            (kw + (((long long)n * RR + t) * FF + ww * 16) * DD2) + lane;
        float4 jqv = *(const float4*)&S->jq[t][lane * 4];
        #pragma unroll
        for (int i = 0; i < 16; i++) {
            float4 kv = __ldg(kr + i * 32);
            float p = kv.x*jqv.x + kv.y*jqv.y + kv.z*jqv.z + kv.w*jqv.w;
            #pragma unroll
            for (int off = 16; off > 0; off >>= 1)
                p += __shfl_xor_sync(0xffffffffu, p, off);
            if (lane == 0) S->v[t][ww * 16 + i] = p;
        }
    }

    // stash w regs to smem
    {
        float4* wdst = (float4*)S->w;
        #pragma unroll
        for (int j = 0; j < 8; j++)
            wdst[tid + 256 * j] = wreg[j];
    }

    // hn gather: 1024 float4 from embed (L2-resident), 4 per thread
    #pragma unroll
    for (int j = 0; j < 4; j++) {
        int i  = tid + 256 * j;
        int t2 = i >> 9, rem = i & 511;
        int kk = rem >> 4, dv = rem & 15;
        *(float4*)(&S->hn[t2][kk][dv * 4]) =
            *(const float4*)(embed + (long long)S->nb[t2][kk] * DD + dv * 4);
    }
    __syncthreads();

    // ---- u[d] = sum_f w[d,f]*v[f] (smem) -------------------------------
    {
        int l16 = lane & 15, half = lane >> 4;
        float4 vv = *(const float4*)&S->v[t][l16 * 4];
        #pragma unroll
        for (int i = 0; i < 8; i++) {
            int d = ww * 16 + i * 2 + half;
            float4 wr4 = *(const float4*)&S->w[t][d * FF + l16 * 4];
            float p = wr4.x*vv.x + wr4.y*vv.y + wr4.z*vv.z + wr4.w*vv.w;
            p += __shfl_xor_sync(0xffffffffu, p, 1);
            p += __shfl_xor_sync(0xffffffffu, p, 2);
            p += __shfl_xor_sync(0xffffffffu, p, 4);
            p += __shfl_xor_sync(0xffffffffu, p, 8);
            if (l16 == 0) S->u[t][d] = p;
        }
    }
    __syncthreads();

    // ---- scores[k] = hn[k,:].u -----------------------------------------
    if ((tid & 127) < 32) {
        int t2 = tid >> 7, kk = tid & 31;
        float s = 0.f;
        #pragma unroll 8
        for (int f = 0; f < FF; f++)
            s += S->hn[t2][kk][f] * S->u[t2][f];
        S->sc[t2][kk] = s;
    }
    __syncthreads();

    // ---- softmax over K=32 (warp 0 -> r0, warp 4 -> r1) ----------------
    if ((tid & 127) < 32) {
        int t2 = tid >> 7;
        float s = S->sc[t2][lane];
        float m = s;
        #pragma unroll
        for (int off = 16; off > 0; off >>= 1)
            m = fmaxf(m, __shfl_xor_sync(0xffffffffu, m, off));
        float e = __expf(s - m);
        float sum = e;
        #pragma unroll
        for (int off = 16; off > 0; off >>= 1)
            sum += __shfl_xor_sync(0xffffffffu, sum, off);
        S->sc[t2][lane] = e / sum;
    }
    __syncthreads();

    // ---- g[d] = sum_k E[k]*hn[k,d] -------------------------------------
    if ((tid & 127) < 64) {
        int t2 = tid >> 7, d = tid & 63;
        float gg = 0.f;
        #pragma unroll
        for (int kk = 0; kk < KK; kk++)
            gg += S->sc[t2][kk] * S->hn[t2][kk][d];
        S->g[t2][d] = gg;
    }
    __syncthreads();

    // ---- df[f] = sum_d g[d]*w[d,f] -> scratch --------------------------
    if ((tid & 127) < 64) {
        int t2 = tid >> 7, f = tid & 63;
        float da = 0.f;
        #pragma unroll 8
        for (int d = 0; d < DD; d++)
            da += S->g[t2][d] * S->w[t2][d * FF + f];
        df_g[((long long)n * RR + t2) * FF + f] = da;
    }
}

// ============ gru: GRU + combine (unchanged, 76% DRAM) =================
__global__ __launch_bounds__(256)
void gru_kernel(const void* __restrict__ x_raw,
                const float* __restrict__ embed,
                const float* __restrict__ Wx,
                const float* __restrict__ Wn,
                const float* __restrict__ bx,
                const float* __restrict__ bn,
                float* __restrict__ out)
{
    __shared__ float h_s[DD];
    __shared__ float df_s[RR][FF];
    __shared__ __align__(16) float part[RR][8][5][FF];
    __shared__ __align__(16) float red[RR][6][FF];
    __shared__ float rdf_s[RR][FF];
    __shared__ float gru_s[RR][FF];
    __shared__ int   flags[2];

    const int n   = blockIdx.x;
    const int tid = threadIdx.x;
    const int r   = tid >> 7;
    const int wg  = tid & 127;

    if (tid == 0) {
        const int* xi = (const int*)x_raw;
        int idx64 = (xi[1] == 0) ? 1 : 0;
        flags[0] = idx64;
        flags[1] = idx64 ? (int)((const long long*)x_raw)[n] : xi[n];
    }
    __syncthreads();
    const int xn = flags[1];

    if (tid < DD) h_s[tid] = embed[(long long)xn * DD + tid];
    if (wg < FF)  df_s[r][wg] = df_g[((long long)n * RR + r) * FF + wg];
    __syncthreads();

    const long long nr = (long long)n * RR + r;
    const float* Wxr = Wx + nr * (3 * DD * FF);
    const float* Wnr = Wn + nr * (3 * FF * FF);
    const float* bxr = bx + nr * (3 * FF);
    const float* bnr = bn + nr * (3 * FF);

    const int fg = wg & 15;
    const int ds = wg >> 4;
    const int f4 = fg * 4;

    float4 a0 = make_float4(0,0,0,0), a1 = a0, a2v = a0, a3 = a0, a4 = a0;
    #pragma unroll
    for (int dd = 0; dd < 8; dd++) {
        int d = ds * 8 + dd;
        float hd  = h_s[d];
        float dfd = df_s[r][d];
        float4 x0 = __ldg((const float4*)(Wxr + (0*DD + d)*FF + f4));
        float4 x1 = __ldg((const float4*)(Wxr + (1*DD + d)*FF + f4));
        float4 x2 = __ldg((const float4*)(Wxr + (2*DD + d)*FF + f4));
        float4 n0 = __ldg((const float4*)(Wnr + (0*FF + d)*FF + f4));
        float4 n1 = __ldg((const float4*)(Wnr + (1*FF + d)*FF + f4));
        a0.x += hd*x0.x;  a0.y += hd*x0.y;  a0.z += hd*x0.z;  a0.w += hd*x0.w;
        a1.x += hd*x1.x;  a1.y += hd*x1.y;  a1.z += hd*x1.z;  a1.w += hd*x1.w;
        a2v.x+= hd*x2.x;  a2v.y+= hd*x2.y;  a2v.z+= hd*x2.z;  a2v.w+= hd*x2.w;
        a3.x += dfd*n0.x; a3.y += dfd*n0.y; a3.z += dfd*n0.z; a3.w += dfd*n0.w;
        a4.x += dfd*n1.x; a4.y += dfd*n1.y; a4.z += dfd*n1.z; a4.w += dfd*n1.w;
    }
    *(float4*)&part[r][ds][0][f4] = a0;
    *(float4*)&part[r][ds][1][f4] = a1;
    *(float4*)&part[r][ds][2][f4] = a2v;
    *(float4*)&part[r][ds][3][f4] = a3;
    *(float4*)&part[r][ds][4][f4] = a4;
    __syncthreads();

    if (wg < 80) {
        int gate = wg >> 4, fgi = wg & 15;
        float4 s = make_float4(0,0,0,0);
        #pragma unroll
        for (int d2 = 0; d2 < 8; d2++) {
            float4 v = *(const float4*)&part[r][d2][gate][fgi * 4];
            s.x += v.x; s.y += v.y; s.z += v.z; s.w += v.w;
        }
        *(float4*)&red[r][gate][fgi * 4] = s;
    }
    __syncthreads();

    float xh_v = 0.f, z_v = 0.f, dff = 0.f;
    if (wg < FF) {
        int f = wg;
        float xr = red[r][0][f] + __ldg(bxr + f);
        float xz = red[r][1][f] + __ldg(bxr + FF + f);
        xh_v     = red[r][2][f] + __ldg(bxr + 2*FF + f);
        float rg = sigm(xr + red[r][3][f] + __ldg(bnr + f));
        z_v      = sigm(xz + red[r][4][f] + __ldg(bnr + FF + f));
        dff = df_s[r][f];
        rdf_s[r][f] = rg * dff;
    }
    __syncthreads();

    float4 c = make_float4(0,0,0,0);
    #pragma unroll
    for (int dd = 0; dd < 8; dd++) {
        int d = ds * 8 + dd;
        float rd = rdf_s[r][d];
        float4 n2 = __ldg((const float4*)(Wnr + (2*FF + d)*FF + f4));
        c.x += rd*n2.x; c.y += rd*n2.y; c.z += rd*n2.z; c.w += rd*n2.w;
    }
    *(float4*)&part[r][ds][0][f4] = c;
    __syncthreads();

    if (wg < 16) {
        float4 s = make_float4(0,0,0,0);
        #pragma unroll
        for (int d2 = 0; d2 < 8; d2++) {
            float4 v = *(const float4*)&part[r][d2][0][wg * 4];
            s.x += v.x; s.y += v.y; s.z += v.z; s.w += v.w;
        }
        *(float4*)&red[r][5][wg * 4] = s;
    }
    __syncthreads();

    if (wg < FF) {
        float hc = tanhf(xh_v + red[r][5][wg] + __ldg(bnr + 2*FF + wg));
        gru_s[r][wg] = z_v * dff + (1.f - z_v) * hc;
    }
    __syncthreads();

    if (tid < FF)
        out[(long long)n * FF + tid] =
            tanhf(0.5f * (gru_s[0][tid] + gru_s[1][tid]));
}

extern "C" void kernel_launch(void* const* d_in, const int* in_sizes, int n_in,
                              void* d_out, int out_size) {
    (void)in_sizes; (void)n_in; (void)out_size;
    cudaFuncSetAttribute(kCD_kernel,
                         cudaFuncAttributeMaxDynamicSharedMemorySize,
                         CD_SMEM_BYTES);
    kJ_kernel<<<NN, 256>>>(
        d_in[0],
        (const float*)d_in[2],         // embed
        (const float*)d_in[3]);        // w
    kJq_kernel<<<NT / 4, 256>>>(
        (const float*)d_in[4]);        // qw
    kCD_kernel<<<NN, 256, CD_SMEM_BYTES>>>(
        d_in[0], d_in[1],
        (const float*)d_in[2],         // embed
        (const float*)d_in[3],         // w
        (const float*)d_in[5]);        // kw
    gru_kernel<<<NN, 256>>>(
        d_in[0],
        (const float*)d_in[2],         // embed
        (const float*)d_in[6],         // Wx
        (const float*)d_in[7],         // Wn
        (const float*)d_in[8],         // bx
        (const float*)d_in[9],         // bn
        (float*)d_out);
}

// round 12
// speedup vs baseline: 1.5624x; 1.0870x over previous
#include <cuda_runtime.h>
#include <cstdint>

// DeepUDI as SIX single-stream kernels. Invariant: each kernel issues exactly
// one large dependency-free DRAM stream in its first instructions; all
// dependent math is a tiny smem tail. CTA staggering keeps HBM saturated.
//   kJ     : w   67MB  -> J
//   kJq    : qw 134MB  -> Jq
//   kV     : kw 134MB  -> v
//   kDF    : w   67MB (cp.async) + hn gather -> u,scores,softmax,g -> df
//   kGates : Wx+Wn01 335MB -> rdf, xh, z
//   kHc    : Wn2 67MB  -> Hc -> out

#define NN   2048
#define RR   2
#define KK   32
#define DD   64
#define FF   64
#define DD2  128
#define HPAD 68
#define NT   (NN * RR)

__device__ float J_g  [NT * FF];       // 1MB
__device__ float Jq_g [NT * DD2];      // 2MB
__device__ float v_g  [NT * FF];       // 1MB
__device__ float df_g [NT * FF];       // 1MB
__device__ float rdf_g[NT * FF];       // 1MB
__device__ float xh_g [NT * FF];       // 1MB
__device__ float z_g  [NT * FF];       // 1MB

__device__ __forceinline__ float sigm(float v) {
    return 1.f / (1.f + __expf(-v));
}
__device__ __forceinline__ void cp16(void* dst, const void* src) {
    uint32_t d = (uint32_t)__cvta_generic_to_shared(dst);
    asm volatile("cp.async.cg.shared.global [%0], [%1], 16;\n" :: "r"(d), "l"(src));
}
#define CP_COMMIT() asm volatile("cp.async.commit_group;\n" ::: "memory")
#define CP_WAIT0()  asm volatile("cp.async.wait_group 0;\n" ::: "memory")

// ============ kJ: J = h @ w ============================================
__global__ __launch_bounds__(256)
void kJ_kernel(const void* __restrict__ x_raw,
               const float* __restrict__ embed,
               const float* __restrict__ w)
{
    __shared__ float h_s[DD];
    __shared__ __align__(16) float part[RR][8][FF];
    __shared__ int flags[2];

    const int n   = blockIdx.x;
    const int tid = threadIdx.x;
    const int r   = tid >> 7;
    const int wg  = tid & 127;
    const int ds  = wg >> 4;
    const int f4  = (wg & 15) * 4;

    const float* wr = w + ((long long)n * RR + r) * (DD * FF);
    float4 wv[8];
    #pragma unroll
    for (int dd = 0; dd < 8; dd++)
        wv[dd] = __ldg((const float4*)(wr + (ds * 8 + dd) * FF + f4));

    if (tid == 0) {
        const int* xi = (const int*)x_raw;
        int idx64 = (xi[1] == 0) ? 1 : 0;
        flags[0] = idx64;
        flags[1] = idx64 ? (int)((const long long*)x_raw)[n] : xi[n];
    }
    __syncthreads();
    if (tid < DD) h_s[tid] = embed[(long long)flags[1] * DD + tid];
    __syncthreads();

    float4 a = make_float4(0, 0, 0, 0);
    #pragma unroll
    for (int dd = 0; dd < 8; dd++) {
        float hd = h_s[ds * 8 + dd];
        a.x += hd * wv[dd].x; a.y += hd * wv[dd].y;
        a.z += hd * wv[dd].z; a.w += hd * wv[dd].w;
    }
    *(float4*)&part[r][ds][f4] = a;
    __syncthreads();

    if (tid < 128) {
        int rr = tid >> 6, f = tid & 63;
        float s = 0.f;
        #pragma unroll
        for (int d2 = 0; d2 < 8; d2++) s += part[rr][d2][f];
        J_g[((long long)n * RR + rr) * FF + f] = s;
    }
}

// ============ kJq: Jq = J @ qw, 4 tiles/CTA ============================
__global__ __launch_bounds__(256)
void kJq_kernel(const float* __restrict__ qw)
{
    __shared__ float J_s[4][FF];
    __shared__ __align__(16) float part[4][8][DD2];

    const int t0  = blockIdx.x * 4;
    const int tid = threadIdx.x;

    {
        int t = tid >> 6, f = tid & 63;
        J_s[t][f] = J_g[(long long)(t0 + t) * FF + f];
    }
    __syncthreads();

    const int e4 = tid & 31;
    const int fh = tid >> 5;

    float4 a0 = make_float4(0,0,0,0), a1 = a0, a2 = a0, a3 = a0;
    const float4* q0 = (const float4*)(qw + ((long long)(t0+0) * FF + fh*8) * DD2) + e4;
    const float4* q1 = (const float4*)(qw + ((long long)(t0+1) * FF + fh*8) * DD2) + e4;
    const float4* q2 = (const float4*)(qw + ((long long)(t0+2) * FF + fh*8) * DD2) + e4;
    const float4* q3 = (const float4*)(qw + ((long long)(t0+3) * FF + fh*8) * DD2) + e4;

    #pragma unroll
    for (int f = 0; f < 8; f++) {
        int ff = fh * 8 + f;
        float j0 = J_s[0][ff], j1 = J_s[1][ff];
        float j2 = J_s[2][ff], j3 = J_s[3][ff];
        float4 v0 = __ldg(q0 + f * 32);
        float4 v1 = __ldg(q1 + f * 32);
        float4 v2 = __ldg(q2 + f * 32);
        float4 v3 = __ldg(q3 + f * 32);
        a0.x += j0*v0.x; a0.y += j0*v0.y; a0.z += j0*v0.z; a0.w += j0*v0.w;
        a1.x += j1*v1.x; a1.y += j1*v1.y; a1.z += j1*v1.z; a1.w += j1*v1.w;
        a2.x += j2*v2.x; a2.y += j2*v2.y; a2.z += j2*v2.z; a2.w += j2*v2.w;
        a3.x += j3*v3.x; a3.y += j3*v3.y; a3.z += j3*v3.z; a3.w += j3*v3.w;
    }
    *(float4*)&part[0][fh][e4 * 4] = a0;
    *(float4*)&part[1][fh][e4 * 4] = a1;
    *(float4*)&part[2][fh][e4 * 4] = a2;
    *(float4*)&part[3][fh][e4 * 4] = a3;
    __syncthreads();

    if (tid < 128) {
        int t = tid >> 5, e = tid & 31;
        float4 s = make_float4(0,0,0,0);
        #pragma unroll
        for (int h = 0; h < 8; h++) {
            float4 v = *(const float4*)&part[t][h][e * 4];
            s.x += v.x; s.y += v.y; s.z += v.z; s.w += v.w;
        }
        *(float4*)(Jq_g + (long long)(t0 + t) * DD2 + e * 4) = s;
    }
}

// ============ kV: v = kw @ Jq, 4 tiles/CTA =============================
__global__ __launch_bounds__(256)
void kV_kernel(const float* __restrict__ kw)
{
    __shared__ __align__(16) float jq_s[4][DD2];

    const int t0  = blockIdx.x * 4;
    const int tid = threadIdx.x;

    {
        int i = tid, t = i >> 7, e = i & 127;
        jq_s[t][e] = Jq_g[(long long)(t0 + t) * DD2 + e];
        i = tid + 256; t = i >> 7; e = i & 127;
        jq_s[t][e] = Jq_g[(long long)(t0 + t) * DD2 + e];
    }
    __syncthreads();

    const int wp = tid >> 5, lane = tid & 31;
    const int tw = wp >> 1;                 // tile for this warp
    const int rb = (wp & 1) * 32;           // row base
    float4 q = *(const float4*)&jq_s[tw][lane * 4];
    const float4* kr = (const float4*)
        (kw + ((long long)(t0 + tw) * FF + rb) * DD2) + lane;

    #pragma unroll 8
    for (int i = 0; i < 32; i++) {
        float4 kv = __ldg(kr + i * 32);
        float p = kv.x*q.x + kv.y*q.y + kv.z*q.z + kv.w*q.w;
        #pragma unroll
        for (int off = 16; off > 0; off >>= 1)
            p += __shfl_xor_sync(0xffffffffu, p, off);
        if (lane == 0)
            v_g[(long long)(t0 + tw) * FF + rb + i] = p;
    }
}

// ============ kDF: u = w@v; scores; softmax; g; df = g@w ===============
struct DFSmem {
    float w [RR][DD * FF];    // 32KB
    float hn[RR][KK][HPAD];   // 17.4KB
    float v [RR][FF];
    float u [RR][FF];
    float sc[RR][KK];
    float g [RR][FF];
    int   nb[RR][KK];
};
#define DF_SMEM_BYTES ((int)sizeof(DFSmem))

__global__ __launch_bounds__(256)
void kDF_kernel(const void* __restrict__ x_raw,
                const void* __restrict__ nb_raw,
                const float* __restrict__ embed,
                const float* __restrict__ w)
{
    extern __shared__ __align__(16) char smem_raw[];
    DFSmem* S = (DFSmem*)smem_raw;

    const int n    = blockIdx.x;
    const int tid  = threadIdx.x;
    const int wp   = tid >> 5;
    const int lane = tid & 31;
    const int t    = wp >> 2;
    const int ww   = wp & 3;

    // front-issue the w stream (cp.async: zero regs, fully async)
    const float4* wsrc = (const float4*)(w + (long long)n * RR * (DD * FF));
    #pragma unroll
    for (int j = 0; j < 8; j++)
        cp16(((float4*)S->w) + tid + 256 * j, wsrc + tid + 256 * j);
    CP_COMMIT();

    const int idx64 = (((const int*)x_raw)[1] == 0) ? 1 : 0;

    if (tid < 64) {
        int tt = tid >> 5, kk = tid & 31;
        long long base = ((long long)n * RR + tt) * KK + kk;
        S->nb[tt][kk] = idx64 ? (int)((const long long*)nb_raw)[base]
                              : ((const int*)nb_raw)[base];
    }
    if (tid >= 128) {
        int i = tid - 128, tt = i >> 6, f = i & 63;
        S->v[tt][f] = v_g[((long long)n * RR + tt) * FF + f];
    }
    __syncthreads();

    // hn gather (embed L2-resident): 1024 float4, 4/thread
    #pragma unroll
    for (int j = 0; j < 4; j++) {
        int i  = tid + 256 * j;
        int t2 = i >> 9, rem = i & 511;
        int kk = rem >> 4, dv = rem & 15;
        *(float4*)(&S->hn[t2][kk][dv * 4]) =
            *(const float4*)(embed + (long long)S->nb[t2][kk] * DD + dv * 4);
    }
    CP_WAIT0();
    __syncthreads();

    // u[d] = sum_f w[d,f]*v[f]
    {
        int l16 = lane & 15, half = lane >> 4;
        float4 vv = *(const float4*)&S->v[t][l16 * 4];
        #pragma unroll
        for (int i = 0; i < 8; i++) {
            int d = ww * 16 + i * 2 + half;
            float4 wr4 = *(const float4*)&S->w[t][d * FF + l16 * 4];
            float p = wr4.x*vv.x + wr4.y*vv.y + wr4.z*vv.z + wr4.w*vv.w;
            p += __shfl_xor_sync(0xffffffffu, p, 1);
            p += __shfl_xor_sync(0xffffffffu, p, 2);
            p += __shfl_xor_sync(0xffffffffu, p, 4);
            p += __shfl_xor_sync(0xffffffffu, p, 8);
            if (l16 == 0) S->u[t][d] = p;
        }
    }
    __syncthreads();

    // scores[k] = hn[k,:].u
    if ((tid & 127) < 32) {
        int t2 = tid >> 7, kk = tid & 31;
        float s = 0.f;
        #pragma unroll 8
        for (int f = 0; f < FF; f++)
            s += S->hn[t2][kk][f] * S->u[t2][f];
        S->sc[t2][kk] = s;
    }
    __syncthreads();

    // softmax over K=32
    if ((tid & 127) < 32) {
        int t2 = tid >> 7;
        float s = S->sc[t2][lane];
        float m = s;
        #pragma unroll
        for (int off = 16; off > 0; off >>= 1)
            m = fmaxf(m, __shfl_xor_sync(0xffffffffu, m, off));
        float e = __expf(s - m);
        float sum = e;
        #pragma unroll
        for (int off = 16; off > 0; off >>= 1)
            sum += __shfl_xor_sync(0xffffffffu, sum, off);
        S->sc[t2][lane] = e / sum;
    }
    __syncthreads();

    // g[d] = sum_k E[k]*hn[k,d]
    if ((tid & 127) < 64) {
        int t2 = tid >> 7, d = tid & 63;
        float gg = 0.f;
        #pragma unroll
        for (int kk = 0; kk < KK; kk++)
            gg += S->sc[t2][kk] * S->hn[t2][kk][d];
        S->g[t2][d] = gg;
    }
    __syncthreads();

    // df[f] = sum_d g[d]*w[d,f]
    if ((tid & 127) < 64) {
        int t2 = tid >> 7, f = tid & 63;
        float da = 0.f;
        #pragma unroll 8
        for (int d = 0; d < DD; d++)
            da += S->g[t2][d] * S->w[t2][d * FF + f];
        df_g[((long long)n * RR + t2) * FF + f] = da;
    }
}

// ============ kGates: 5 matvecs -> rdf, xh, z ==========================
__global__ __launch_bounds__(256)
void kGates_kernel(const void* __restrict__ x_raw,
                   const float* __restrict__ embed,
                   const float* __restrict__ Wx,
                   const float* __restrict__ Wn,
                   const float* __restrict__ bx,
                   const float* __restrict__ bn)
{
    __shared__ float h_s[DD];
    __shared__ float df_s[RR][FF];
    __shared__ __align__(16) float part[RR][8][5][FF];
    __shared__ __align__(16) float red[RR][5][FF];
    __shared__ int flags[2];

    const int n   = blockIdx.x;
    const int tid = threadIdx.x;
    const int r   = tid >> 7;
    const int wg  = tid & 127;

    if (tid == 0) {
        const int* xi = (const int*)x_raw;
        int idx64 = (xi[1] == 0) ? 1 : 0;
        flags[0] = idx64;
        flags[1] = idx64 ? (int)((const long long*)x_raw)[n] : xi[n];
    }
    __syncthreads();
    const int xn = flags[1];

    if (tid < DD) h_s[tid] = embed[(long long)xn * DD + tid];
    if (wg < FF)  df_s[r][wg] = df_g[((long long)n * RR + r) * FF + wg];
    __syncthreads();

    const long long nr = (long long)n * RR + r;
    const float* Wxr = Wx + nr * (3 * DD * FF);
    const float* Wnr = Wn + nr * (3 * FF * FF);
    const float* bxr = bx + nr * (3 * FF);
    const float* bnr = bn + nr * (3 * FF);

    const int ds = wg >> 4;
    const int f4 = (wg & 15) * 4;

    float4 a0 = make_float4(0,0,0,0), a1 = a0, a2v = a0, a3 = a0, a4 = a0;
    #pragma unroll
    for (int dd = 0; dd < 8; dd++) {
        int d = ds * 8 + dd;
        float hd  = h_s[d];
        float dfd = df_s[r][d];
        float4 x0 = __ldg((const float4*)(Wxr + (0*DD + d)*FF + f4));
        float4 x1 = __ldg((const float4*)(Wxr + (1*DD + d)*FF + f4));
        float4 x2 = __ldg((const float4*)(Wxr + (2*DD + d)*FF + f4));
        float4 n0 = __ldg((const float4*)(Wnr + (0*FF + d)*FF + f4));
        float4 n1 = __ldg((const float4*)(Wnr + (1*FF + d)*FF + f4));
        a0.x += hd*x0.x;  a0.y += hd*x0.y;  a0.z += hd*x0.z;  a0.w += hd*x0.w;
        a1.x += hd*x1.x;  a1.y += hd*x1.y;  a1.z += hd*x1.z;  a1.w += hd*x1.w;
        a2v.x+= hd*x2.x;  a2v.y+= hd*x2.y;  a2v.z+= hd*x2.z;  a2v.w+= hd*x2.w;
        a3.x += dfd*n0.x; a3.y += dfd*n0.y; a3.z += dfd*n0.z; a3.w += dfd*n0.w;
        a4.x += dfd*n1.x; a4.y += dfd*n1.y; a4.z += dfd*n1.z; a4.w += dfd*n1.w;
    }
    *(float4*)&part[r][ds][0][f4] = a0;
    *(float4*)&part[r][ds][1][f4] = a1;
    *(float4*)&part[r][ds][2][f4] = a2v;
    *(float4*)&part[r][ds][3][f4] = a3;
    *(float4*)&part[r][ds][4][f4] = a4;
    __syncthreads();

    if (wg < 80) {
        int gate = wg >> 4, fgi = wg & 15;
        float4 s = make_float4(0,0,0,0);
        #pragma unroll
        for (int d2 = 0; d2 < 8; d2++) {
            float4 v = *(const float4*)&part[r][d2][gate][fgi * 4];
            s.x += v.x; s.y += v.y; s.z += v.z; s.w += v.w;
        }
        *(float4*)&red[r][gate][fgi * 4] = s;
    }
    __syncthreads();

    if (wg < FF) {
        int f = wg;
        float xr = red[r][0][f] + __ldg(bxr + f);
        float xz = red[r][1][f] + __ldg(bxr + FF + f);
        float xh = red[r][2][f] + __ldg(bxr + 2*FF + f);
        float rg = sigm(xr + red[r][3][f] + __ldg(bnr + f));
        float z  = sigm(xz + red[r][4][f] + __ldg(bnr + FF + f));
        float dff = df_s[r][f];
        rdf_g[nr * FF + f] = rg * dff;
        xh_g [nr * FF + f] = xh;
        z_g  [nr * FF + f] = z;
    }
}

// ============ kHc: c = rdf@Wn2; Hc; combine; out =======================
__global__ __launch_bounds__(256)
void kHc_kernel(const float* __restrict__ Wn,
                const float* __restrict__ bn,
                float* __restrict__ out)
{
    __shared__ float rdf_s[RR][FF];
    __shared__ __align__(16) float part[RR][8][FF];
    __shared__ float gru_s[RR][FF];

    const int n   = blockIdx.x;
    const int tid = threadIdx.x;
    const int r   = tid >> 7;
    const int wg  = tid & 127;
    const int ds  = wg >> 4;
    const int f4  = (wg & 15) * 4;

    const long long nr = (long long)n * RR + r;
    const float* Wn2 = Wn + nr * (3 * FF * FF) + 2 * FF * FF;

    // front-issue Wn2: 8 independent LDG.128
    float4 wv[8];
    #pragma unroll
    for (int dd = 0; dd < 8; dd++)
        wv[dd] = __ldg((const float4*)(Wn2 + (ds * 8 + dd) * FF + f4));

    if (wg < FF) rdf_s[r][wg] = rdf_g[nr * FF + wg];
    __syncthreads();

    float4 a = make_float4(0, 0, 0, 0);
    #pragma unroll
    for (int dd = 0; dd < 8; dd++) {
        float rd = rdf_s[r][ds * 8 + dd];
        a.x += rd * wv[dd].x; a.y += rd * wv[dd].y;
        a.z += rd * wv[dd].z; a.w += rd * wv[dd].w;
    }
    *(float4*)&part[r][ds][f4] = a;
    __syncthreads();

    if (wg < FF) {
        float c = 0.f;
        #pragma unroll
        for (int d2 = 0; d2 < 8; d2++) c += part[r][d2][wg];
        float xh  = xh_g[nr * FF + wg];
        float z   = z_g [nr * FF + wg];
        float dff = df_g[nr * FF + wg];
        float hc = tanhf(xh + c + __ldg(bn + nr * (3 * FF) + 2 * FF + wg));
        gru_s[r][wg] = z * dff + (1.f - z) * hc;
    }
    __syncthreads();

    if (tid < FF)
        out[(long long)n * FF + tid] =
            tanhf(0.5f * (gru_s[0][tid] + gru_s[1][tid]));
}

extern "C" void kernel_launch(void* const* d_in, const int* in_sizes, int n_in,
                              void* d_out, int out_size) {
    (void)in_sizes; (void)n_in; (void)out_size;
    cudaFuncSetAttribute(kDF_kernel,
                         cudaFuncAttributeMaxDynamicSharedMemorySize,
                         DF_SMEM_BYTES);
    kJ_kernel<<<NN, 256>>>(
        d_in[0],
        (const float*)d_in[2],         // embed
        (const float*)d_in[3]);        // w
    kJq_kernel<<<NT / 4, 256>>>(
        (const float*)d_in[4]);        // qw
    kV_kernel<<<NT / 4, 256>>>(
        (const float*)d_in[5]);        // kw
    kDF_kernel<<<NN, 256, DF_SMEM_BYTES>>>(
        d_in[0], d_in[1],
        (const float*)d_in[2],         // embed
        (const float*)d_in[3]);        // w
    kGates_kernel<<<NN, 256>>>(
        d_in[0],
        (const float*)d_in[2],         // embed
        (const float*)d_in[6],         // Wx
        (const float*)d_in[7],         // Wn
        (const float*)d_in[8],         // bx
        (const float*)d_in[9]);        // bn
    kHc_kernel<<<NN, 256>>>(
        (const float*)d_in[7],         // Wn
        (const float*)d_in[9],         // bn
        (float*)d_out);
}